// round 16
// baseline (speedup 1.0000x reference)
#include <cuda_runtime.h>
#include <math.h>

#define BB   8192
#define TT   21
#define NTY  10
#define VT   5000

typedef unsigned long long ull;

// ---------------- device scratch ----------------
__device__ __align__(16) float g_tokproj[2][VT][96];
__device__ __align__(16) float g_holeproj[2][96];
__device__ __align__(16) float g_tmax[21][32][BB];
// gx0 pair layout: [d][t][jpair(48)][b(BB)][2]
__device__ __align__(16) float g_gx0[2][21][48][BB][2];
__device__ __align__(16) float g_y0[21][64][BB];
__device__ int   g_mask_kind;

// ---------------- packed f32x2 helpers ----------------
__device__ __forceinline__ ull pk2(float lo, float hi) {
    ull r; asm("mov.b64 %0, {%1,%2};" : "=l"(r) : "f"(lo), "f"(hi)); return r;
}
__device__ __forceinline__ ull bc2(float v) {
    ull r; asm("mov.b64 %0, {%1,%1};" : "=l"(r) : "f"(v)); return r;
}
__device__ __forceinline__ void upk2(ull v, float& lo, float& hi) {
    asm("mov.b64 {%0,%1}, %2;" : "=f"(lo), "=f"(hi) : "l"(v));
}
__device__ __forceinline__ ull fma2(ull a, ull b, ull c) {
    ull d; asm("fma.rn.f32x2 %0, %1, %2, %3;" : "=l"(d) : "l"(a), "l"(b), "l"(c)); return d;
}
__device__ __forceinline__ ull ld2(const float* p) { return *(const ull*)p; }
__device__ __forceinline__ void st2(float* p, ull v) { *(ull*)p = v; }

__device__ __forceinline__ float sigmoidf_(float x) {
    return __fdividef(1.0f, 1.0f + __expf(-x));
}
__device__ __forceinline__ float tanhf_(float x) {
    x = fminf(fmaxf(x, -15.0f), 15.0f);
    float e = __expf(2.0f * x);
    return __fdividef(e - 1.0f, e + 1.0f);
}

// ---------------- mask dtype detection ----------------
__global__ void k_detect(const unsigned char* __restrict__ m) {
    __shared__ int s_nonbin, s_off;
    if (threadIdx.x == 0) { s_nonbin = 0; s_off = 0; }
    __syncthreads();
    int nonbin = 0, off = 0;
    for (int i = threadIdx.x; i < 4096; i += blockDim.x) {
        unsigned char v = m[i];
        if (v > 1) nonbin = 1;
        if ((i & 3) != 0 && v == 1) off = 1;
    }
    if (nonbin) atomicOr(&s_nonbin, 1);
    if (off)    atomicOr(&s_off, 1);
    __syncthreads();
    if (threadIdx.x == 0)
        g_mask_kind = s_nonbin ? 2 : (s_off ? 1 : 0);
}

// ---------------- vocab / hole projection through layer0 x-rows ----------------
__global__ void k_tokproj(const float* __restrict__ te, const float* __restrict__ hole,
                          const float* __restrict__ gkf, const float* __restrict__ gbf,
                          const float* __restrict__ ckf, const float* __restrict__ cbf,
                          const float* __restrict__ gkb, const float* __restrict__ gbb,
                          const float* __restrict__ ckb, const float* __restrict__ cbb) {
    __shared__ float sx[160];
    int v = blockIdx.x;
    int tid = threadIdx.x;
    bool is_hole = (v == VT);
    int xl = is_hole ? 160 : 128;
    if (is_hole) { if (tid < 160) sx[tid] = hole[tid]; }
    else         { if (tid < 128) sx[tid] = te[v * 128 + tid]; }
    __syncthreads();
    int d = tid / 96, j = tid % 96;
    const float* gk = d ? gkb : gkf;
    const float* ck = d ? ckb : ckf;
    const float* gb = d ? gbb : gbf;
    const float* cb = d ? cbb : cbf;
    float acc = (j < 64) ? gb[j] : cb[j - 64];
    if (j < 64) {
        for (int k = 0; k < xl; k++) acc += sx[k] * gk[k * 64 + j];
    } else {
        int jj = j - 64;
        for (int k = 0; k < xl; k++) acc += sx[k] * ck[k * 32 + jj];
    }
    if (is_hole) g_holeproj[d][j] = acc;
    else         g_tokproj[d][v][j] = acc;
}

// ---------------- masked max over type embeddings ----------------
__global__ void k_typemax(const int* __restrict__ types_b, const void* __restrict__ mask_b,
                          const int* __restrict__ types_a, const void* __restrict__ mask_a,
                          const float* __restrict__ typ_emb) {
    int kg = threadIdx.x, lbv = threadIdx.y;
    int b = blockIdx.x * 32 + lbv;
    int p = blockIdx.y;
    int t = (p < 10) ? p : p + 1;
    const int*  types = (p < 10) ? types_b : types_a;
    const void* maskp = (p < 10) ? mask_b : mask_a;
    int pp = (p < 10) ? p : p - 10;
    int mk = g_mask_kind;
    int base = (b * NTY + pp) * NTY;
    int k0 = kg * 4;
    float m0 = -3.4e38f, m1 = -3.4e38f, m2 = -3.4e38f, m3 = -3.4e38f;
    #pragma unroll
    for (int nt = 0; nt < NTY; nt++) {
        int id = types[base + nt];
        bool valid;
        if (mk == 0)      valid = ((const int*)maskp)[base + nt] != 0;
        else if (mk == 1) valid = ((const unsigned char*)maskp)[base + nt] != 0;
        else              valid = ((const float*)maskp)[base + nt] != 0.0f;
        float pen = valid ? 0.0f : -1000.0f;
        float4 e = *(const float4*)(typ_emb + id * 32 + k0);
        m0 = fmaxf(m0, e.x + pen);
        m1 = fmaxf(m1, e.y + pen);
        m2 = fmaxf(m2, e.z + pen);
        m3 = fmaxf(m3, e.w + pen);
    }
    g_tmax[t][k0 + 0][b] = m0;
    g_tmax[t][k0 + 1][b] = m1;
    g_tmax[t][k0 + 2][b] = m2;
    g_tmax[t][k0 + 3][b] = m3;
}

// ---------------- layer0 x-projection: weight-major f32x2, pair-layout output ----------------
// grid (BB/64, 21, 2), block (32,8); thread handles b = base+2*lb, base+2*lb+1, jpairs jg*6..+5
__global__ __launch_bounds__(256) void k_x0(const int* __restrict__ tok_b, const int* __restrict__ tok_a,
                     const float* __restrict__ gkf, const float* __restrict__ ckf,
                     const float* __restrict__ gkb, const float* __restrict__ ckb) {
    int d = blockIdx.z, t = blockIdx.y;
    int lb = threadIdx.x, jg = threadIdx.y;
    int b0 = blockIdx.x * 64 + 2 * lb;
    __shared__ __align__(16) float sW[32][96];
    __shared__ float sX[64][97];
    __shared__ int   stok[64];
    const float* gk = d ? gkb : gkf;
    const float* ck = d ? ckb : ckf;
    int tid = jg * 32 + lb;
    for (int i = tid; i < 32 * 96; i += 256) {
        int k = i / 96, j = i % 96;
        sW[k][j] = (j < 64) ? gk[(128 + k) * 64 + j] : ck[(128 + k) * 32 + (j - 64)];
    }
    float* outI = &g_gx0[d][t][0][0][0];
    int j0 = jg * 12;
    int jp0 = jg * 6;
    if (t == 10) {
        #pragma unroll
        for (int p = 0; p < 6; p++) {
            ull hv = ld2(&g_holeproj[d][j0 + 2 * p]);
            ulonglong2 o; o.x = hv; o.y = hv;
            *(ulonglong2*)(outI + ((size_t)(jp0 + p) * BB + b0) * 2) = o;
        }
        return;
    }
    int pp = (t < 10) ? t : t - 11;
    if (tid < 64) {
        int bg = blockIdx.x * 64 + tid;
        stok[tid] = (t < 10) ? tok_b[bg * NTY + pp] : tok_a[bg * NTY + pp];
    }
    __syncthreads();
    for (int i = tid; i < 64 * 24; i += 256) {
        int row = i / 24, q = i - row * 24;
        float4 v = ((const float4*)&g_tokproj[d][stok[row]][0])[q];
        sX[row][q * 4 + 0] = v.x;
        sX[row][q * 4 + 1] = v.y;
        sX[row][q * 4 + 2] = v.z;
        sX[row][q * 4 + 3] = v.w;
    }
    __syncthreads();
    ull acc0[6], acc1[6];   // jpairs for batch b0, b1
    #pragma unroll
    for (int p = 0; p < 6; p++) {
        acc0[p] = pk2(sX[2 * lb][j0 + 2 * p], sX[2 * lb][j0 + 2 * p + 1]);
        acc1[p] = pk2(sX[2 * lb + 1][j0 + 2 * p], sX[2 * lb + 1][j0 + 2 * p + 1]);
    }
    const float* tm = &g_tmax[t][0][0];
    #pragma unroll
    for (int k = 0; k < 32; k++) {
        float t0, t1;
        upk2(ld2(&tm[(size_t)k * BB + b0]), t0, t1);
        ull tb0 = bc2(t0), tb1 = bc2(t1);
        const ull* w2 = (const ull*)&sW[k][j0];
        #pragma unroll
        for (int p = 0; p < 6; p++) {
            ull w = w2[p];
            acc0[p] = fma2(tb0, w, acc0[p]);
            acc1[p] = fma2(tb1, w, acc1[p]);
        }
    }
    #pragma unroll
    for (int p = 0; p < 6; p++) {
        ulonglong2 o; o.x = acc0[p]; o.y = acc1[p];
        *(ulonglong2*)(outI + ((size_t)(jp0 + p) * BB + b0) * 2) = o;
    }
}

// ---------------- layer0 recurrent scan: weight-major f32x2, pair-layout gx ----------------
// grid (BB/64, 2), block (32,8)
__global__ __launch_bounds__(256) void k_scan(const float* __restrict__ gx, float* __restrict__ y,
                       const float* __restrict__ gkf, const float* __restrict__ ckf,
                       const float* __restrict__ gkb, const float* __restrict__ ckb,
                       int hoff) {
    int d = blockIdx.y;
    int lb = threadIdx.x, jg = threadIdx.y;
    int b0 = blockIdx.x * 64 + 2 * lb;
    const float* gk = d ? gkb : gkf;
    const float* ck = d ? ckb : ckf;
    __shared__ __align__(16) float sWg[32][64];
    __shared__ __align__(16) float sWc[32][32];
    __shared__ ull sH[32][33];
    __shared__ ull sRH[32][33];
    __shared__ ull sU[32][33];
    int tid = jg * 32 + lb;
    for (int i = tid; i < 32 * 64; i += 256) { int k = i / 64, j = i % 64; sWg[k][j] = gk[(hoff + k) * 64 + j]; }
    for (int i = tid; i < 32 * 32; i += 256) { int k = i / 32, j = i % 32; sWc[k][j] = ck[(hoff + k) * 32 + j]; }
    for (int i = tid; i < 32 * 32; i += 256) { sH[i / 32][i % 32] = 0ULL; }
    __syncthreads();
    const float* gxd = gx + (size_t)d * TT * 48 * BB * 2;
    int ycol = d ? 32 : 0;
    int j0 = jg * 8;
    int jc0 = jg * 4;
    int jpg0 = jg * 4;       // gate jpair base
    int jpc0 = 32 + jg * 2;  // candidate jpair base
    ull a0[4], a1[4], c0[2], c1[2];
    {
        int t0 = d ? TT - 1 : 0;
        #pragma unroll
        for (int jp = 0; jp < 4; jp++) {
            ulonglong2 v = *(const ulonglong2*)(gxd + ((size_t)(t0 * 48 + jpg0 + jp) * BB + b0) * 2);
            a0[jp] = v.x; a1[jp] = v.y;
        }
        #pragma unroll
        for (int jp = 0; jp < 2; jp++) {
            ulonglong2 v = *(const ulonglong2*)(gxd + ((size_t)(t0 * 48 + jpc0 + jp) * BB + b0) * 2);
            c0[jp] = v.x; c1[jp] = v.y;
        }
    }
    for (int s = 0; s < TT; s++) {
        int t = d ? (TT - 1 - s) : s;
        // prefetch next step's gx
        ull na0[4], na1[4], nc0[2], nc1[2];
        {
            int s2 = (s + 1 < TT) ? s + 1 : s;
            int t2 = d ? (TT - 1 - s2) : s2;
            #pragma unroll
            for (int jp = 0; jp < 4; jp++) {
                ulonglong2 v = *(const ulonglong2*)(gxd + ((size_t)(t2 * 48 + jpg0 + jp) * BB + b0) * 2);
                na0[jp] = v.x; na1[jp] = v.y;
            }
            #pragma unroll
            for (int jp = 0; jp < 2; jp++) {
                ulonglong2 v = *(const ulonglong2*)(gxd + ((size_t)(t2 * 48 + jpc0 + jp) * BB + b0) * 2);
                nc0[jp] = v.x; nc1[jp] = v.y;
            }
        }
        // ---- gate h-recurrence ----
        #pragma unroll
        for (int k = 0; k < 32; k++) {
            float hlo, hhi;
            upk2(sH[lb][k], hlo, hhi);
            ull hb0 = bc2(hlo), hb1 = bc2(hhi);
            const ull* w2 = (const ull*)&sWg[k][j0];
            #pragma unroll
            for (int jp = 0; jp < 4; jp++) {
                ull w = w2[jp];
                a0[jp] = fma2(hb0, w, a0[jp]);
                a1[jp] = fma2(hb1, w, a1[jp]);
            }
        }
        if (jg < 4) {
            #pragma unroll
            for (int jp = 0; jp < 4; jp++) {
                int kk = j0 + 2 * jp;
                float x0, x1, y0_, y1_;
                upk2(a0[jp], x0, x1);
                upk2(a1[jp], y0_, y1_);
                float h0lo, h0hi, h1lo, h1hi;
                upk2(sH[lb][kk], h0lo, h0hi);
                upk2(sH[lb][kk + 1], h1lo, h1hi);
                sRH[lb][kk]     = pk2(sigmoidf_(x0) * h0lo, sigmoidf_(y0_) * h0hi);
                sRH[lb][kk + 1] = pk2(sigmoidf_(x1) * h1lo, sigmoidf_(y1_) * h1hi);
            }
        } else {
            #pragma unroll
            for (int jp = 0; jp < 4; jp++) {
                int kk = j0 + 2 * jp - 32;
                float x0, x1, y0_, y1_;
                upk2(a0[jp], x0, x1);
                upk2(a1[jp], y0_, y1_);
                sU[lb][kk]     = pk2(sigmoidf_(x0), sigmoidf_(y0_));
                sU[lb][kk + 1] = pk2(sigmoidf_(x1), sigmoidf_(y1_));
            }
        }
        __syncthreads();
        // ---- candidate recurrence ----
        ull cc0[2], cc1[2];
        #pragma unroll
        for (int jp = 0; jp < 2; jp++) { cc0[jp] = c0[jp]; cc1[jp] = c1[jp]; }
        #pragma unroll
        for (int k = 0; k < 32; k++) {
            float rlo, rhi;
            upk2(sRH[lb][k], rlo, rhi);
            ull rb0 = bc2(rlo), rb1 = bc2(rhi);
            const ull* w2 = (const ull*)&sWc[k][jc0];
            #pragma unroll
            for (int jp = 0; jp < 2; jp++) {
                ull w = w2[jp];
                cc0[jp] = fma2(rb0, w, cc0[jp]);
                cc1[jp] = fma2(rb1, w, cc1[jp]);
            }
        }
        // ---- update + output ----
        float* yout = y + (size_t)t * 64 * BB + (size_t)ycol * BB + b0;
        #pragma unroll
        for (int jp = 0; jp < 2; jp++) {
            int kk = jc0 + 2 * jp;
            float cb0lo, cb0hi, cb1lo, cb1hi;
            upk2(cc0[jp], cb0lo, cb0hi);
            upk2(cc1[jp], cb1lo, cb1hi);
            cb0lo = tanhf_(cb0lo); cb0hi = tanhf_(cb0hi);
            cb1lo = tanhf_(cb1lo); cb1hi = tanhf_(cb1hi);
            float u0lo, u0hi, u1lo, u1hi;
            upk2(sU[lb][kk], u0lo, u0hi);
            upk2(sU[lb][kk + 1], u1lo, u1hi);
            float h0lo, h0hi, h1lo, h1hi;
            upk2(sH[lb][kk], h0lo, h0hi);
            upk2(sH[lb][kk + 1], h1lo, h1hi);
            float hnA0 = u0lo * h0lo + (1.0f - u0lo) * cb0lo;   // (b0, kk)
            float hnB0 = u0hi * h0hi + (1.0f - u0hi) * cb1lo;   // (b1, kk)
            float hnA1 = u1lo * h1lo + (1.0f - u1lo) * cb0hi;   // (b0, kk+1)
            float hnB1 = u1hi * h1hi + (1.0f - u1hi) * cb1hi;   // (b1, kk+1)
            ull hn0 = pk2(hnA0, hnB0);
            ull hn1 = pk2(hnA1, hnB1);
            sH[lb][kk] = hn0;
            sH[lb][kk + 1] = hn1;
            st2(&yout[(size_t)kk * BB], hn0);
            st2(&yout[(size_t)(kk + 1) * BB], hn1);
        }
        #pragma unroll
        for (int jp = 0; jp < 4; jp++) { a0[jp] = na0[jp]; a1[jp] = na1[jp]; }
        #pragma unroll
        for (int jp = 0; jp < 2; jp++) { c0[jp] = nc0[jp]; c1[jp] = nc1[jp]; }
        __syncthreads();
    }
}

// ---------------- layer1 FUSED scan: weight-major f32x2 x-projection from y0 ----------------
// grid (BB/64, 2), block (32,8), dynamic smem. Writes out[b][t][i] directly.
#define SM1F_BYTES 94976
__global__ __launch_bounds__(256) void k_scan1f(const float* __restrict__ y0g, float* __restrict__ out,
                        const float* __restrict__ gkf, const float* __restrict__ gbf,
                        const float* __restrict__ ckf, const float* __restrict__ cbf,
                        const float* __restrict__ gkb, const float* __restrict__ gbb,
                        const float* __restrict__ ckb, const float* __restrict__ cbb) {
    extern __shared__ __align__(16) char dsm[];
    float* sW1 = (float*)dsm;                 // [64][96]
    float* sWg = sW1 + 64 * 96;               // [32][64]
    float* sWc = sWg + 32 * 64;               // [32][32]
    ull*   sH  = (ull*)(sWc + 32 * 32);       // [32][33]
    ull*   sRH = sH + 32 * 33;
    ull*   sU  = sRH + 32 * 33;
    float* sY  = (float*)(sU + 32 * 33);      // [2][64][64]

    int d = blockIdx.y;
    int lb = threadIdx.x, jg = threadIdx.y;
    int bb = blockIdx.x * 64;
    int b0 = bb + 2 * lb;
    const float* gk = d ? gkb : gkf;
    const float* ck = d ? ckb : ckf;
    const float* gb = d ? gbb : gbf;
    const float* cb = d ? cbb : cbf;
    int tid = jg * 32 + lb;
    for (int i = tid; i < 64 * 96; i += 256) {
        int k = i / 96, j = i % 96;
        sW1[i] = (j < 64) ? gk[k * 64 + j] : ck[k * 32 + (j - 64)];
    }
    for (int i = tid; i < 32 * 64; i += 256) { int k = i / 64, j = i % 64; sWg[i] = gk[(64 + k) * 64 + j]; }
    for (int i = tid; i < 32 * 32; i += 256) { int k = i / 32, j = i % 32; sWc[i] = ck[(64 + k) * 32 + j]; }
    for (int i = tid; i < 32 * 32; i += 256) { sH[(i / 32) * 33 + (i % 32)] = 0ULL; }
    int j0 = jg * 8;
    int jc0 = jg * 4;
    // bias pairs (same for both batches)
    ull bgp[4], bcp[2];
    #pragma unroll
    for (int jp = 0; jp < 4; jp++) bgp[jp] = ld2(&gb[j0 + 2 * jp]);
    #pragma unroll
    for (int jp = 0; jp < 2; jp++) bcp[jp] = ld2(&cb[jc0 + 2 * jp]);
    // prologue: stage step-0 tile
    {
        int t0 = d ? TT - 1 : 0;
        const float* src = y0g + (size_t)t0 * 64 * BB + bb;
        for (int i = tid; i < 64 * 64; i += 256) {
            int k = i >> 6, c = i & 63;
            sY[k * 64 + c] = src[(size_t)k * BB + c];
        }
    }
    __syncthreads();
    int ycol = d ? 32 : 0;
    int prow = tid >> 2;
    int pc0  = (tid & 3) * 16;
    for (int s = 0; s < TT; s++) {
        int t = d ? (TT - 1 - s) : s;
        int buf = s & 1;
        const float* sYb = sY + buf * 4096;
        // prefetch next tile
        float4 p0, p1, p2, p3;
        {
            int s2 = (s + 1 < TT) ? s + 1 : s;
            int t2 = d ? (TT - 1 - s2) : s2;
            const float4* src = (const float4*)(y0g + (size_t)(t2 * 64 + prow) * BB + bb + pc0);
            p0 = src[0]; p1 = src[1]; p2 = src[2]; p3 = src[3];
        }
        // ---- phase 1: x-projection (64 k) + gate recurrence (32 k), weight-major ----
        ull a0[4], a1[4], c0[2], c1[2];
        #pragma unroll
        for (int jp = 0; jp < 4; jp++) { a0[jp] = bgp[jp]; a1[jp] = bgp[jp]; }
        #pragma unroll
        for (int jp = 0; jp < 2; jp++) { c0[jp] = bcp[jp]; c1[jp] = bcp[jp]; }
        #pragma unroll 8
        for (int k = 0; k < 64; k++) {
            float ylo, yhi;
            upk2(*(const ull*)&sYb[k * 64 + 2 * lb], ylo, yhi);
            ull yb0 = bc2(ylo), yb1 = bc2(yhi);
            const float* wr = &sW1[k * 96];
            const ull* wg2 = (const ull*)&wr[j0];
            const ull* wc2 = (const ull*)&wr[64 + jc0];
            #pragma unroll
            for (int jp = 0; jp < 4; jp++) {
                ull w = wg2[jp];
                a0[jp] = fma2(yb0, w, a0[jp]);
                a1[jp] = fma2(yb1, w, a1[jp]);
            }
            #pragma unroll
            for (int jp = 0; jp < 2; jp++) {
                ull w = wc2[jp];
                c0[jp] = fma2(yb0, w, c0[jp]);
                c1[jp] = fma2(yb1, w, c1[jp]);
            }
        }
        #pragma unroll
        for (int k = 0; k < 32; k++) {
            float hlo, hhi;
            upk2(sH[lb * 33 + k], hlo, hhi);
            ull hb0 = bc2(hlo), hb1 = bc2(hhi);
            const ull* w2 = (const ull*)&sWg[k * 64 + j0];
            #pragma unroll
            for (int jp = 0; jp < 4; jp++) {
                ull w = w2[jp];
                a0[jp] = fma2(hb0, w, a0[jp]);
                a1[jp] = fma2(hb1, w, a1[jp]);
            }
        }
        if (jg < 4) {
            #pragma unroll
            for (int jp = 0; jp < 4; jp++) {
                int kk = j0 + 2 * jp;
                float x0, x1, y0_, y1_;
                upk2(a0[jp], x0, x1);
                upk2(a1[jp], y0_, y1_);
                float h0lo, h0hi, h1lo, h1hi;
                upk2(sH[lb * 33 + kk], h0lo, h0hi);
                upk2(sH[lb * 33 + kk + 1], h1lo, h1hi);
                sRH[lb * 33 + kk]     = pk2(sigmoidf_(x0) * h0lo, sigmoidf_(y0_) * h0hi);
                sRH[lb * 33 + kk + 1] = pk2(sigmoidf_(x1) * h1lo, sigmoidf_(y1_) * h1hi);
            }
        } else {
            #pragma unroll
            for (int jp = 0; jp < 4; jp++) {
                int kk = j0 + 2 * jp - 32;
                float x0, x1, y0_, y1_;
                upk2(a0[jp], x0, x1);
                upk2(a1[jp], y0_, y1_);
                sU[lb * 33 + kk]     = pk2(sigmoidf_(x0), sigmoidf_(y0_));
                sU[lb * 33 + kk + 1] = pk2(sigmoidf_(x1), sigmoidf_(y1_));
            }
        }
        __syncthreads();
        // ---- phase 2: candidate recurrence + update + direct output ----
        #pragma unroll
        for (int k = 0; k < 32; k++) {
            float rlo, rhi;
            upk2(sRH[lb * 33 + k], rlo, rhi);
            ull rb0 = bc2(rlo), rb1 = bc2(rhi);
            const ull* w2 = (const ull*)&sWc[k * 32 + jc0];
            #pragma unroll
            for (int jp = 0; jp < 2; jp++) {
                ull w = w2[jp];
                c0[jp] = fma2(rb0, w, c0[jp]);
                c1[jp] = fma2(rb1, w, c1[jp]);
            }
        }
        float f0[4], f1[4];
        #pragma unroll
        for (int jp = 0; jp < 2; jp++) {
            int kk = jc0 + 2 * jp;
            float cb0lo, cb0hi, cb1lo, cb1hi;
            upk2(c0[jp], cb0lo, cb0hi);
            upk2(c1[jp], cb1lo, cb1hi);
            cb0lo = tanhf_(cb0lo); cb0hi = tanhf_(cb0hi);
            cb1lo = tanhf_(cb1lo); cb1hi = tanhf_(cb1hi);
            float u0lo, u0hi, u1lo, u1hi;
            upk2(sU[lb * 33 + kk], u0lo, u0hi);
            upk2(sU[lb * 33 + kk + 1], u1lo, u1hi);
            float h0lo, h0hi, h1lo, h1hi;
            upk2(sH[lb * 33 + kk], h0lo, h0hi);
            upk2(sH[lb * 33 + kk + 1], h1lo, h1hi);
            float hnA0 = u0lo * h0lo + (1.0f - u0lo) * cb0lo;
            float hnB0 = u0hi * h0hi + (1.0f - u0hi) * cb1lo;
            float hnA1 = u1lo * h1lo + (1.0f - u1lo) * cb0hi;
            float hnB1 = u1hi * h1hi + (1.0f - u1hi) * cb1hi;
            sH[lb * 33 + kk]     = pk2(hnA0, hnB0);
            sH[lb * 33 + kk + 1] = pk2(hnA1, hnB1);
            f0[2 * jp] = hnA0; f0[2 * jp + 1] = hnA1;
            f1[2 * jp] = hnB0; f1[2 * jp + 1] = hnB1;
        }
        float* ob = out + (size_t)b0 * (TT * 64) + t * 64 + ycol + jc0;
        *(float4*)ob = make_float4(f0[0], f0[1], f0[2], f0[3]);
        *(float4*)(ob + TT * 64) = make_float4(f1[0], f1[1], f1[2], f1[3]);
        // stage prefetched tile
        float* sYn = sY + (buf ^ 1) * 4096 + prow * 64 + pc0;
        ((float4*)sYn)[0] = p0;
        ((float4*)sYn)[1] = p1;
        ((float4*)sYn)[2] = p2;
        ((float4*)sYn)[3] = p3;
        __syncthreads();
    }
}

// ---------------- launch ----------------
extern "C" void kernel_launch(void* const* d_in, const int* in_sizes, int n_in,
                              void* d_out, int out_size) {
    const int*   tokens_before = (const int*)d_in[0];
    const int*   types_before  = (const int*)d_in[1];
    const void*  mask_before   = d_in[2];
    const int*   tokens_after  = (const int*)d_in[3];
    const int*   types_after   = (const int*)d_in[4];
    const void*  mask_after    = d_in[5];
    const float* token_emb     = (const float*)d_in[6];
    const float* type_emb      = (const float*)d_in[7];
    const float* hole          = (const float*)d_in[8];
    const float* gk_fw0 = (const float*)d_in[9];
    const float* gb_fw0 = (const float*)d_in[10];
    const float* ck_fw0 = (const float*)d_in[11];
    const float* cb_fw0 = (const float*)d_in[12];
    const float* gk_bw0 = (const float*)d_in[13];
    const float* gb_bw0 = (const float*)d_in[14];
    const float* ck_bw0 = (const float*)d_in[15];
    const float* cb_bw0 = (const float*)d_in[16];
    const float* gk_fw1 = (const float*)d_in[17];
    const float* gb_fw1 = (const float*)d_in[18];
    const float* ck_fw1 = (const float*)d_in[19];
    const float* cb_fw1 = (const float*)d_in[20];
    const float* gk_bw1 = (const float*)d_in[21];
    const float* gb_bw1 = (const float*)d_in[22];
    const float* ck_bw1 = (const float*)d_in[23];
    const float* cb_bw1 = (const float*)d_in[24];
    float* out = (float*)d_out;

    float* gx0; cudaGetSymbolAddress((void**)&gx0, g_gx0);
    float* y0;  cudaGetSymbolAddress((void**)&y0,  g_y0);

    cudaFuncSetAttribute(k_scan1f, cudaFuncAttributeMaxDynamicSharedMemorySize, SM1F_BYTES);

    k_detect<<<1, 256>>>((const unsigned char*)mask_before);
    k_typemax<<<dim3(BB / 32, 20), dim3(8, 32)>>>(types_before, mask_before, types_after, mask_after, type_emb);
    k_tokproj<<<VT + 1, 192>>>(token_emb, hole,
                               gk_fw0, gb_fw0, ck_fw0, cb_fw0,
                               gk_bw0, gb_bw0, ck_bw0, cb_bw0);
    k_x0<<<dim3(BB / 64, TT, 2), dim3(32, 8)>>>(tokens_before, tokens_after,
                                                gk_fw0, ck_fw0, gk_bw0, ck_bw0);
    k_scan<<<dim3(BB / 64, 2), dim3(32, 8)>>>(gx0, y0, gk_fw0, ck_fw0, gk_bw0, ck_bw0, 160);
    k_scan1f<<<dim3(BB / 64, 2), dim3(32, 8), SM1F_BYTES>>>(y0, out,
                                                gk_fw1, gb_fw1, ck_fw1, cb_fw1,
                                                gk_bw1, gb_bw1, ck_bw1, cb_bw1);
}